// round 16
// baseline (speedup 1.0000x reference)
#include <cuda_runtime.h>
#include <cuda_bf16.h>
#include <math.h>
#include <stdint.h>

#define NB 256
#define ZD 1024
#define HD 2048
#define NT 128
#define NP (NB * ZD)

#define KCH 16            // k elements per chunk
#define NCHUNK 16         // K slab = 256 per CTA
#define SPLIT1 4          // GEMM1 split-K (1024/256)
#define SPLIT2 8          // GEMM2 split-K (2048/256)
#define OFF_ALO 4096      // region offsets inside a stage
#define OFF_BHI 8192
#define OFF_BLO 10240
#define STAGE 12288       // Ahi 4K + Alo 4K + Bhi 2K + Blo 2K
#define STAGES 3          // 36864 B static smem -> 2 CTAs/SM

// ---------------- device scratch ------------------------------------------
__device__ float g_hp[SPLIT1][NB * HD];   // GEMM1 split-K partials
__device__ float g_dzp[SPLIT2][NB * ZD];  // GEMM2 split-K partials
__device__ float g_z[NP];
__device__ float g_traj[NT * NP];
__device__ __nv_bfloat16 g_zhi[NP], g_zlo[NP];
__device__ __nv_bfloat16 g_hhi[NB * HD], g_hlo[NB * HD];
__device__ __nv_bfloat16 g_W1hi[HD * ZD], g_W1lo[HD * ZD];
__device__ __nv_bfloat16 g_W2hi[ZD * HD], g_W2lo[ZD * HD];

// ---------------- PTX helpers ---------------------------------------------
__device__ __forceinline__ void cp16(uint32_t dst, const void *src) {
    asm volatile("cp.async.cg.shared.global [%0], [%1], 16;" :: "r"(dst), "l"(src));
}
__device__ __forceinline__ void cp_commit() {
    asm volatile("cp.async.commit_group;" ::: "memory");
}
template <int N>
__device__ __forceinline__ void cp_wait() {
    asm volatile("cp.async.wait_group %0;" :: "n"(N) : "memory");
}
__device__ __forceinline__ void ldsm4(uint32_t &r0, uint32_t &r1, uint32_t &r2,
                                      uint32_t &r3, uint32_t a) {
    asm volatile("ldmatrix.sync.aligned.m8n8.x4.shared.b16 {%0,%1,%2,%3}, [%4];"
                 : "=r"(r0), "=r"(r1), "=r"(r2), "=r"(r3) : "r"(a));
}
__device__ __forceinline__ void mma16816(float *c, const uint32_t *a,
                                         const uint32_t *b) {
    asm volatile(
        "mma.sync.aligned.m16n8k16.row.col.f32.bf16.bf16.f32 "
        "{%0,%1,%2,%3}, {%4,%5,%6,%7}, {%8,%9}, {%0,%1,%2,%3};"
        : "+f"(c[0]), "+f"(c[1]), "+f"(c[2]), "+f"(c[3])
        : "r"(a[0]), "r"(a[1]), "r"(a[2]), "r"(a[3]), "r"(b[0]), "r"(b[1]));
}
__device__ __forceinline__ void bf16_split(float v, __nv_bfloat16 &hi,
                                           __nv_bfloat16 &lo) {
    hi = __float2bfloat16_rn(v);
    lo = __float2bfloat16_rn(v - __bfloat162float(hi));
}
__device__ __forceinline__ uint32_t pack2(__nv_bfloat16 a, __nv_bfloat16 b) {
    return (uint32_t)__bfloat16_as_ushort(a) |
           ((uint32_t)__bfloat16_as_ushort(b) << 16);
}
// swizzled byte offset inside one region (row r, 16B-column c16 in {0,1})
__device__ __forceinline__ uint32_t swz(uint32_t r, uint32_t c16) {
    return r * 32u + ((c16 ^ ((r >> 2) & 1u)) << 4);
}

// ---------------- warp-MMA GEMM (128m x 64n CTA tile, 256 thr, split-K) ----
// Register-pipelined: mma on chunk c overlaps ldsm of chunk c+1.
// D[m,n] = sum_k A[m,k]*B[n,k] via 3 bf16 products (hi*hi + hi*lo + lo*hi).
// MODE 0: A = z splits (LDA=1024), B = W1 splits; out -> g_hp[z]
// MODE 1: A = h splits (LDA=2048), B = W2 splits; out -> g_dzp[z]
template <int LDA, int MODE>
__global__ void __launch_bounds__(256, 2)
gemm_mma() {
    __shared__ __align__(128) char smem[STAGES * STAGE];
    const uint32_t s0 = (uint32_t)__cvta_generic_to_shared(smem);

    const int tid = threadIdx.x;
    const int wid = tid >> 5, l = tid & 31;
    const int wm = wid & 3, wn = wid >> 2;        // warp grid 4(m) x 2(n)
    const int g = l >> 2, tig = l & 3;

    const int m0 = blockIdx.y * 128, n0 = blockIdx.x * 64;
    const int kOff = (int)blockIdx.z * (NCHUNK * KCH);

    const __nv_bfloat16 *Ahi = MODE ? g_hhi : g_zhi;
    const __nv_bfloat16 *Alo = MODE ? g_hlo : g_zlo;
    const __nv_bfloat16 *Bhi = MODE ? g_W2hi : g_W1hi;
    const __nv_bfloat16 *Blo = MODE ? g_W2lo : g_W1lo;

    // ---- loader lane constants ----
    const int aRow = tid >> 1;                    // 0..127
    const int aC = tid & 1;                       // 16B half
    const uint32_t aSw = swz(aRow, aC);
    const __nv_bfloat16 *pAh = Ahi + (size_t)(m0 + aRow) * LDA + kOff + aC * 8;
    const __nv_bfloat16 *pAl = Alo + (size_t)(m0 + aRow) * LDA + kOff + aC * 8;
    const int bRow = (tid & 127) >> 1;
    const int bC = tid & 1;
    const int bLo = tid >> 7;                     // 0: hi, 1: lo
    const uint32_t bSw = (uint32_t)(OFF_BHI + bLo * 2048) + swz(bRow, bC);
    const __nv_bfloat16 *pB =
        (bLo ? Blo : Bhi) + (size_t)(n0 + bRow) * LDA + kOff + bC * 8;

    // ---- ldmatrix lane offsets ----
    uint32_t offA[2], offB[2];
#pragma unroll
    for (int mt = 0; mt < 2; mt++)
        offA[mt] = swz((uint32_t)(wm * 32 + mt * 16 + (l & 15)), (uint32_t)(l >> 4));
#pragma unroll
    for (int np = 0; np < 2; np++)
        offB[np] = swz((uint32_t)(wn * 32 + np * 16 + ((l >> 4) << 3) + (l & 7)),
                       (uint32_t)((l >> 3) & 1));

    float acc[2][4][4];
#pragma unroll
    for (int mt = 0; mt < 2; mt++)
#pragma unroll
        for (int nt = 0; nt < 4; nt++)
#pragma unroll
            for (int i = 0; i < 4; i++) acc[mt][nt][i] = 0.0f;

    auto load = [&](int c, int st) {
        const uint32_t sb = s0 + (uint32_t)st * STAGE;
        const int e = c * KCH;
        cp16(sb + aSw, pAh + e);
        cp16(sb + OFF_ALO + aSw, pAl + e);
        cp16(sb + bSw, pB + e);
        cp_commit();
    };

    uint32_t aF[2][2][2][4], bF[2][2][2][4];   // [buf][split][tile][4]
    auto ldsm_chunk = [&](uint32_t sb, int buf) {
#pragma unroll
        for (int mt = 0; mt < 2; mt++) {
            ldsm4(aF[buf][0][mt][0], aF[buf][0][mt][1], aF[buf][0][mt][2],
                  aF[buf][0][mt][3], sb + offA[mt]);
            ldsm4(aF[buf][1][mt][0], aF[buf][1][mt][1], aF[buf][1][mt][2],
                  aF[buf][1][mt][3], sb + OFF_ALO + offA[mt]);
        }
#pragma unroll
        for (int np = 0; np < 2; np++) {
            ldsm4(bF[buf][0][np][0], bF[buf][0][np][1], bF[buf][0][np][2],
                  bF[buf][0][np][3], sb + OFF_BHI + offB[np]);
            ldsm4(bF[buf][1][np][0], bF[buf][1][np][1], bF[buf][1][np][2],
                  bF[buf][1][np][3], sb + OFF_BLO + offB[np]);
        }
    };

    // ---- prologue: stages 0,1 in flight; frags for chunk 0 in registers ----
    load(0, 0);
    load(1, 1);
    cp_wait<1>();           // group 0 done
    __syncthreads();
    ldsm_chunk(s0, 0);

#pragma unroll 1
    for (int c = 0; c < NCHUNK; c++) {
        const int cur = c & 1, nxt = cur ^ 1;
        if (c + 2 < NCHUNK) {
            load(c + 2, (c + 2) % 3);   // overwrite of stage (c-1)%3: readers
            cp_wait<1>();               // fenced by iter c-1 barrier; group c+1 done
        } else {
            cp_wait<0>();
        }
        __syncthreads();                // stage c+1 now CTA-visible
        if (c + 1 < NCHUNK)
            ldsm_chunk(s0 + (uint32_t)((c + 1) % 3) * STAGE, nxt);  // prefetch
#pragma unroll
        for (int mt = 0; mt < 2; mt++)
#pragma unroll
            for (int nt = 0; nt < 4; nt++) {
                const uint32_t *bh = &bF[cur][0][nt >> 1][(nt & 1) * 2];
                const uint32_t *bl = &bF[cur][1][nt >> 1][(nt & 1) * 2];
                mma16816(acc[mt][nt], aF[cur][0][mt], bh);   // hi*hi
                mma16816(acc[mt][nt], aF[cur][0][mt], bl);   // hi*lo
                mma16816(acc[mt][nt], aF[cur][1][mt], bh);   // lo*hi
            }
    }

    // ---- epilogue: raw fp32 partials ----
    const int LDO = MODE ? ZD : HD;
    float *dst = (MODE ? g_dzp[blockIdx.z] : g_hp[blockIdx.z]);
#pragma unroll
    for (int mt = 0; mt < 2; mt++) {
        const int mr = m0 + wm * 32 + mt * 16 + g;
#pragma unroll
        for (int nt = 0; nt < 4; nt++) {
            const int n = n0 + wn * 32 + nt * 8 + tig * 2;
            *(float2 *)(dst + (size_t)mr * LDO + n) =
                make_float2(acc[mt][nt][0], acc[mt][nt][1]);
            *(float2 *)(dst + (size_t)(mr + 8) * LDO + n) =
                make_float2(acc[mt][nt][2], acc[mt][nt][3]);
        }
    }
}

// ---------------- reduce + tanh + split for h ------------------------------
__global__ void __launch_bounds__(256)
hsplit_kernel(const float *__restrict__ wt, const float *__restrict__ b1,
              const float *__restrict__ ts, int step) {
    const int base = (blockIdx.x * 256 + threadIdx.x) * 4;  // < NB*HD
    const float t = ts[step];
    const int n = base & (HD - 1);
    float4 s = *(const float4 *)(g_hp[0] + base);
#pragma unroll
    for (int p = 1; p < SPLIT1; p++) {
        const float4 q = *(const float4 *)(g_hp[p] + base);
        s.x += q.x; s.y += q.y; s.z += q.z; s.w += q.w;
    }
    const float4 w = *(const float4 *)(wt + n);
    const float4 b = *(const float4 *)(b1 + n);
    const float v0 = tanhf(s.x + fmaf(t, w.x, b.x));
    const float v1 = tanhf(s.y + fmaf(t, w.y, b.y));
    const float v2 = tanhf(s.z + fmaf(t, w.z, b.z));
    const float v3 = tanhf(s.w + fmaf(t, w.w, b.w));
    __nv_bfloat16 h[4], l[4];
    bf16_split(v0, h[0], l[0]); bf16_split(v1, h[1], l[1]);
    bf16_split(v2, h[2], l[2]); bf16_split(v3, h[3], l[3]);
    *(uint2 *)(g_hhi + base) = make_uint2(pack2(h[0], h[1]), pack2(h[2], h[3]));
    *(uint2 *)(g_hlo + base) = make_uint2(pack2(l[0], l[1]), pack2(l[2], l[3]));
}

// ---------------- Euler update (SPLIT2 partials) ---------------------------
__global__ void __launch_bounds__(256)
euler_kernel(const float *__restrict__ b2, const float *__restrict__ ts, int step) {
    const int base = (blockIdx.x * 256 + threadIdx.x) * 4;  // < NP
    const float dt = ts[step + 1] - ts[step];
    float4 s = *(const float4 *)(g_dzp[0] + base);
#pragma unroll
    for (int p = 1; p < SPLIT2; p++) {
        const float4 q = *(const float4 *)(g_dzp[p] + base);
        s.x += q.x; s.y += q.y; s.z += q.z; s.w += q.w;
    }
    const float4 z = *(const float4 *)(g_z + base);
    const int n = base & (ZD - 1);
    const float4 bb = *(const float4 *)(b2 + n);
    float4 zn;
    zn.x = fmaf(dt, s.x + bb.x, z.x);
    zn.y = fmaf(dt, s.y + bb.y, z.y);
    zn.z = fmaf(dt, s.z + bb.z, z.z);
    zn.w = fmaf(dt, s.w + bb.w, z.w);
    *(float4 *)(g_z + base) = zn;
    *(float4 *)(g_traj + (size_t)(step + 1) * NP + base) = zn;
    __nv_bfloat16 h[4], l[4];
    bf16_split(zn.x, h[0], l[0]); bf16_split(zn.y, h[1], l[1]);
    bf16_split(zn.z, h[2], l[2]); bf16_split(zn.w, h[3], l[3]);
    *(uint2 *)(g_zhi + base) = make_uint2(pack2(h[0], h[1]), pack2(h[2], h[3]));
    *(uint2 *)(g_zlo + base) = make_uint2(pack2(l[0], l[1]), pack2(l[2], l[3]));
}

__global__ void __launch_bounds__(256)
init_kernel(const float *__restrict__ z0) {
    const int base = (blockIdx.x * 256 + threadIdx.x) * 4;
    const float4 v = *(const float4 *)(z0 + base);
    *(float4 *)(g_z + base) = v;
    *(float4 *)(g_traj + base) = v;
    __nv_bfloat16 h[4], l[4];
    bf16_split(v.x, h[0], l[0]); bf16_split(v.y, h[1], l[1]);
    bf16_split(v.z, h[2], l[2]); bf16_split(v.w, h[3], l[3]);
    *(uint2 *)(g_zhi + base) = make_uint2(pack2(h[0], h[1]), pack2(h[2], h[3]));
    *(uint2 *)(g_zlo + base) = make_uint2(pack2(l[0], l[1]), pack2(l[2], l[3]));
}

__global__ void __launch_bounds__(256)
wsplit_kernel(const float *__restrict__ src, int which) {
    const int base = (blockIdx.x * 256 + threadIdx.x) * 4;
    __nv_bfloat16 *dh = which ? g_W2hi : g_W1hi;
    __nv_bfloat16 *dl = which ? g_W2lo : g_W1lo;
    const float4 v = *(const float4 *)(src + base);
    __nv_bfloat16 h[4], l[4];
    bf16_split(v.x, h[0], l[0]); bf16_split(v.y, h[1], l[1]);
    bf16_split(v.z, h[2], l[2]); bf16_split(v.w, h[3], l[3]);
    *(uint2 *)(dh + base) = make_uint2(pack2(h[0], h[1]), pack2(h[2], h[3]));
    *(uint2 *)(dl + base) = make_uint2(pack2(l[0], l[1]), pack2(l[2], l[3]));
}

// [T][B*Z] -> [B*Z][T]
__global__ void __launch_bounds__(256)
transpose_kernel(float *__restrict__ out) {
    __shared__ float sm[32][33];
    const int p0 = blockIdx.x * 32;
    const int t0 = blockIdx.y * 32;
    const int tx = threadIdx.x;
    const int ty = threadIdx.y;
#pragma unroll
    for (int i = 0; i < 4; i++) {
        const int tl = ty + 8 * i;
        sm[tl][tx] = g_traj[(size_t)(t0 + tl) * NP + p0 + tx];
    }
    __syncthreads();
#pragma unroll
    for (int i = 0; i < 4; i++) {
        const int pl = ty + 8 * i;
        out[(size_t)(p0 + pl) * NT + t0 + tx] = sm[tx][pl];
    }
}

// ---------------------------------------------------------------------------
extern "C" void kernel_launch(void *const *d_in, const int *in_sizes, int n_in,
                              void *d_out, int out_size) {
    const float *z0 = (const float *)d_in[0];
    const float *ts = (const float *)d_in[1];
    const float *W1 = (const float *)d_in[2];
    const float *wt = (const float *)d_in[3];
    const float *b1 = (const float *)d_in[4];
    const float *W2 = (const float *)d_in[5];
    const float *b2 = (const float *)d_in[6];
    float *out = (float *)d_out;

    wsplit_kernel<<<(HD * ZD) / 1024, 256>>>(W1, 0);
    wsplit_kernel<<<(HD * ZD) / 1024, 256>>>(W2, 1);
    init_kernel<<<NP / 1024, 256>>>(z0);

    for (int s = 0; s < NT - 1; ++s) {
        // partials of z @ W1^T (split-K=4): 256 CTAs x 256 thr
        gemm_mma<ZD, 0><<<dim3(HD / 64, NB / 128, SPLIT1), 256>>>();
        // h = tanh(sum + t*wt + b1) -> bf16 splits
        hsplit_kernel<<<(NB * HD) / 1024, 256>>>(wt, b1, ts, s);
        // partials of h @ W2^T (split-K=8): 256 CTAs x 256 thr
        gemm_mma<HD, 1><<<dim3(ZD / 64, NB / 128, SPLIT2), 256>>>();
        // z += dt*(dz + b2); trajectory slice s+1
        euler_kernel<<<NP / 1024, 256>>>(b2, ts, s);
    }

    transpose_kernel<<<dim3(NP / 32, NT / 32), dim3(32, 8)>>>(out);
}

// round 17
// speedup vs baseline: 2.4244x; 2.4244x over previous
#include <cuda_runtime.h>
#include <cuda_bf16.h>
#include <math.h>
#include <stdint.h>

#define NB 256
#define ZD 1024
#define HD 2048
#define NT 128
#define NP (NB * ZD)

#define KCH 16            // k elements per chunk
#define NCHUNK 16         // K slab = 256 per CTA
#define SPLIT1 4          // GEMM1 split-K (1024/256)
#define SPLIT2 8          // GEMM2 split-K (2048/256)
#define OFF_ALO 4096      // region offsets inside a stage
#define OFF_BHI 8192
#define OFF_BLO 10240
#define STAGE 12288       // Ahi 4K + Alo 4K + Bhi 2K + Blo 2K
#define STAGES 3          // 36864 B static smem -> 2 CTAs/SM

// ---------------- device scratch ------------------------------------------
__device__ float g_hp[SPLIT1][NB * HD];   // GEMM1 split-K partials
__device__ float g_dzp[SPLIT2][NB * ZD];  // GEMM2 split-K partials
__device__ float g_z[NP];
__device__ float g_traj[NT * NP];
__device__ __nv_bfloat16 g_zhi[NP], g_zlo[NP];
__device__ __nv_bfloat16 g_hhi[NB * HD], g_hlo[NB * HD];
__device__ __nv_bfloat16 g_W1hi[HD * ZD], g_W1lo[HD * ZD];
__device__ __nv_bfloat16 g_W2hi[ZD * HD], g_W2lo[ZD * HD];

// ---------------- PTX helpers ---------------------------------------------
__device__ __forceinline__ void cp16(uint32_t dst, const void *src) {
    asm volatile("cp.async.cg.shared.global [%0], [%1], 16;" :: "r"(dst), "l"(src));
}
__device__ __forceinline__ void cp_commit() {
    asm volatile("cp.async.commit_group;" ::: "memory");
}
template <int N>
__device__ __forceinline__ void cp_wait() {
    asm volatile("cp.async.wait_group %0;" :: "n"(N) : "memory");
}
__device__ __forceinline__ void ldsm4(uint32_t &r0, uint32_t &r1, uint32_t &r2,
                                      uint32_t &r3, uint32_t a) {
    asm volatile("ldmatrix.sync.aligned.m8n8.x4.shared.b16 {%0,%1,%2,%3}, [%4];"
                 : "=r"(r0), "=r"(r1), "=r"(r2), "=r"(r3) : "r"(a));
}
__device__ __forceinline__ void mma16816(float *c, const uint32_t *a,
                                         const uint32_t *b) {
    asm volatile(
        "mma.sync.aligned.m16n8k16.row.col.f32.bf16.bf16.f32 "
        "{%0,%1,%2,%3}, {%4,%5,%6,%7}, {%8,%9}, {%0,%1,%2,%3};"
        : "+f"(c[0]), "+f"(c[1]), "+f"(c[2]), "+f"(c[3])
        : "r"(a[0]), "r"(a[1]), "r"(a[2]), "r"(a[3]), "r"(b[0]), "r"(b[1]));
}
__device__ __forceinline__ void bf16_split(float v, __nv_bfloat16 &hi,
                                           __nv_bfloat16 &lo) {
    hi = __float2bfloat16_rn(v);
    lo = __float2bfloat16_rn(v - __bfloat162float(hi));
}
__device__ __forceinline__ uint32_t pack2(__nv_bfloat16 a, __nv_bfloat16 b) {
    return (uint32_t)__bfloat16_as_ushort(a) |
           ((uint32_t)__bfloat16_as_ushort(b) << 16);
}
// swizzled byte offset inside one region (row r, 16B-column c16 in {0,1})
__device__ __forceinline__ uint32_t swz(uint32_t r, uint32_t c16) {
    return r * 32u + ((c16 ^ ((r >> 2) & 1u)) << 4);
}

// ---------------- warp-MMA GEMM (128m x 64n CTA tile, 256 thr, split-K) ----
// Register-pipelined with STATIC buffer indices (loop unrolled x2 by hand):
// mma on chunk c (buf X) overlaps ldsm of chunk c+1 (buf Y).
// D[m,n] = sum_k A[m,k]*B[n,k] via 3 bf16 products (hi*hi + hi*lo + lo*hi).
// MODE 0: A = z splits (LDA=1024), B = W1 splits; out -> g_hp[z]
// MODE 1: A = h splits (LDA=2048), B = W2 splits; out -> g_dzp[z]
template <int LDA, int MODE>
__global__ void __launch_bounds__(256, 2)
gemm_mma() {
    __shared__ __align__(128) char smem[STAGES * STAGE];
    const uint32_t s0 = (uint32_t)__cvta_generic_to_shared(smem);

    const int tid = threadIdx.x;
    const int wid = tid >> 5, l = tid & 31;
    const int wm = wid & 3, wn = wid >> 2;        // warp grid 4(m) x 2(n)
    const int g = l >> 2, tig = l & 3;

    const int m0 = blockIdx.y * 128, n0 = blockIdx.x * 64;
    const int kOff = (int)blockIdx.z * (NCHUNK * KCH);

    const __nv_bfloat16 *Ahi = MODE ? g_hhi : g_zhi;
    const __nv_bfloat16 *Alo = MODE ? g_hlo : g_zlo;
    const __nv_bfloat16 *Bhi = MODE ? g_W2hi : g_W1hi;
    const __nv_bfloat16 *Blo = MODE ? g_W2lo : g_W1lo;

    // ---- loader lane constants ----
    const int aRow = tid >> 1;                    // 0..127
    const int aC = tid & 1;                       // 16B half
    const uint32_t aSw = swz(aRow, aC);
    const __nv_bfloat16 *pAh = Ahi + (size_t)(m0 + aRow) * LDA + kOff + aC * 8;
    const __nv_bfloat16 *pAl = Alo + (size_t)(m0 + aRow) * LDA + kOff + aC * 8;
    const int bRow = (tid & 127) >> 1;
    const int bC = tid & 1;
    const int bLo = tid >> 7;                     // 0: hi, 1: lo
    const uint32_t bSw = (uint32_t)(OFF_BHI + bLo * 2048) + swz(bRow, bC);
    const __nv_bfloat16 *pB =
        (bLo ? Blo : Bhi) + (size_t)(n0 + bRow) * LDA + kOff + bC * 8;

    // ---- ldmatrix lane offsets ----
    uint32_t offA[2], offB[2];
#pragma unroll
    for (int mt = 0; mt < 2; mt++)
        offA[mt] = swz((uint32_t)(wm * 32 + mt * 16 + (l & 15)), (uint32_t)(l >> 4));
#pragma unroll
    for (int np = 0; np < 2; np++)
        offB[np] = swz((uint32_t)(wn * 32 + np * 16 + ((l >> 4) << 3) + (l & 7)),
                       (uint32_t)((l >> 3) & 1));

    float acc[2][4][4];
#pragma unroll
    for (int mt = 0; mt < 2; mt++)
#pragma unroll
        for (int nt = 0; nt < 4; nt++)
#pragma unroll
            for (int i = 0; i < 4; i++) acc[mt][nt][i] = 0.0f;

    auto load = [&](int c, int st) {
        const uint32_t sb = s0 + (uint32_t)st * STAGE;
        const int e = c * KCH;
        cp16(sb + aSw, pAh + e);
        cp16(sb + OFF_ALO + aSw, pAl + e);
        cp16(sb + bSw, pB + e);
        cp_commit();
    };

    // frag double-buffer; ONLY ever indexed with literal constants
    uint32_t aF[2][2][2][4], bF[2][2][2][4];   // [buf][split][tile][4]

    // buf is a compile-time literal at every call site -> static after inline
    auto ldsm_chunk = [&](uint32_t sb, const int buf) {
#pragma unroll
        for (int mt = 0; mt < 2; mt++) {
            ldsm4(aF[buf][0][mt][0], aF[buf][0][mt][1], aF[buf][0][mt][2],
                  aF[buf][0][mt][3], sb + offA[mt]);
            ldsm4(aF[buf][1][mt][0], aF[buf][1][mt][1], aF[buf][1][mt][2],
                  aF[buf][1][mt][3], sb + OFF_ALO + offA[mt]);
        }
#pragma unroll
        for (int np = 0; np < 2; np++) {
            ldsm4(bF[buf][0][np][0], bF[buf][0][np][1], bF[buf][0][np][2],
                  bF[buf][0][np][3], sb + OFF_BHI + offB[np]);
            ldsm4(bF[buf][1][np][0], bF[buf][1][np][1], bF[buf][1][np][2],
                  bF[buf][1][np][3], sb + OFF_BLO + offB[np]);
        }
    };
    auto mma_block = [&](const int buf) {
#pragma unroll
        for (int mt = 0; mt < 2; mt++)
#pragma unroll
            for (int nt = 0; nt < 4; nt++) {
                const uint32_t *bh = &bF[buf][0][nt >> 1][(nt & 1) * 2];
                const uint32_t *bl = &bF[buf][1][nt >> 1][(nt & 1) * 2];
                mma16816(acc[mt][nt], aF[buf][0][mt], bh);   // hi*hi
                mma16816(acc[mt][nt], aF[buf][0][mt], bl);   // hi*lo
                mma16816(acc[mt][nt], aF[buf][1][mt], bh);   // lo*hi
            }
    };

    // ---- prologue ----
    load(0, 0);
    load(1, 1);
    cp_wait<1>();           // chunk 0 resident
    __syncthreads();
    ldsm_chunk(s0, 0);

#pragma unroll 1
    for (int c = 0; c < NCHUNK; c += 2) {
        // -- even: mma chunk c (buf 0), prefetch chunk c+1 -> buf 1 --
        if (c + 2 < NCHUNK) { load(c + 2, (c + 2) % 3); cp_wait<1>(); }
        else cp_wait<0>();
        __syncthreads();                 // chunk c+1 CTA-visible
        ldsm_chunk(s0 + (uint32_t)(((c + 1) % 3)) * STAGE, 1);
        mma_block(0);

        // -- odd: mma chunk c+1 (buf 1), prefetch chunk c+2 -> buf 0 --
        if (c + 3 < NCHUNK) { load(c + 3, (c + 3) % 3); cp_wait<1>(); }
        else cp_wait<0>();
        __syncthreads();                 // chunk c+2 CTA-visible
        if (c + 2 < NCHUNK)
            ldsm_chunk(s0 + (uint32_t)(((c + 2) % 3)) * STAGE, 0);
        mma_block(1);
    }

    // ---- epilogue: raw fp32 partials ----
    const int LDO = MODE ? ZD : HD;
    float *dst = (MODE ? g_dzp[blockIdx.z] : g_hp[blockIdx.z]);
#pragma unroll
    for (int mt = 0; mt < 2; mt++) {
        const int mr = m0 + wm * 32 + mt * 16 + g;
#pragma unroll
        for (int nt = 0; nt < 4; nt++) {
            const int n = n0 + wn * 32 + nt * 8 + tig * 2;
            *(float2 *)(dst + (size_t)mr * LDO + n) =
                make_float2(acc[mt][nt][0], acc[mt][nt][1]);
            *(float2 *)(dst + (size_t)(mr + 8) * LDO + n) =
                make_float2(acc[mt][nt][2], acc[mt][nt][3]);
        }
    }
}

// ---------------- reduce + tanh + split for h ------------------------------
__global__ void __launch_bounds__(256)
hsplit_kernel(const float *__restrict__ wt, const float *__restrict__ b1,
              const float *__restrict__ ts, int step) {
    const int base = (blockIdx.x * 256 + threadIdx.x) * 4;  // < NB*HD
    const float t = ts[step];
    const int n = base & (HD - 1);
    float4 s = *(const float4 *)(g_hp[0] + base);
#pragma unroll
    for (int p = 1; p < SPLIT1; p++) {
        const float4 q = *(const float4 *)(g_hp[p] + base);
        s.x += q.x; s.y += q.y; s.z += q.z; s.w += q.w;
    }
    const float4 w = *(const float4 *)(wt + n);
    const float4 b = *(const float4 *)(b1 + n);
    const float v0 = tanhf(s.x + fmaf(t, w.x, b.x));
    const float v1 = tanhf(s.y + fmaf(t, w.y, b.y));
    const float v2 = tanhf(s.z + fmaf(t, w.z, b.z));
    const float v3 = tanhf(s.w + fmaf(t, w.w, b.w));
    __nv_bfloat16 h[4], l[4];
    bf16_split(v0, h[0], l[0]); bf16_split(v1, h[1], l[1]);
    bf16_split(v2, h[2], l[2]); bf16_split(v3, h[3], l[3]);
    *(uint2 *)(g_hhi + base) = make_uint2(pack2(h[0], h[1]), pack2(h[2], h[3]));
    *(uint2 *)(g_hlo + base) = make_uint2(pack2(l[0], l[1]), pack2(l[2], l[3]));
}

// ---------------- Euler update (SPLIT2 partials) ---------------------------
__global__ void __launch_bounds__(256)
euler_kernel(const float *__restrict__ b2, const float *__restrict__ ts, int step) {
    const int base = (blockIdx.x * 256 + threadIdx.x) * 4;  // < NP
    const float dt = ts[step + 1] - ts[step];
    float4 s = *(const float4 *)(g_dzp[0] + base);
#pragma unroll
    for (int p = 1; p < SPLIT2; p++) {
        const float4 q = *(const float4 *)(g_dzp[p] + base);
        s.x += q.x; s.y += q.y; s.z += q.z; s.w += q.w;
    }
    const float4 z = *(const float4 *)(g_z + base);
    const int n = base & (ZD - 1);
    const float4 bb = *(const float4 *)(b2 + n);
    float4 zn;
    zn.x = fmaf(dt, s.x + bb.x, z.x);
    zn.y = fmaf(dt, s.y + bb.y, z.y);
    zn.z = fmaf(dt, s.z + bb.z, z.z);
    zn.w = fmaf(dt, s.w + bb.w, z.w);
    *(float4 *)(g_z + base) = zn;
    *(float4 *)(g_traj + (size_t)(step + 1) * NP + base) = zn;
    __nv_bfloat16 h[4], l[4];
    bf16_split(zn.x, h[0], l[0]); bf16_split(zn.y, h[1], l[1]);
    bf16_split(zn.z, h[2], l[2]); bf16_split(zn.w, h[3], l[3]);
    *(uint2 *)(g_zhi + base) = make_uint2(pack2(h[0], h[1]), pack2(h[2], h[3]));
    *(uint2 *)(g_zlo + base) = make_uint2(pack2(l[0], l[1]), pack2(l[2], l[3]));
}

__global__ void __launch_bounds__(256)
init_kernel(const float *__restrict__ z0) {
    const int base = (blockIdx.x * 256 + threadIdx.x) * 4;
    const float4 v = *(const float4 *)(z0 + base);
    *(float4 *)(g_z + base) = v;
    *(float4 *)(g_traj + base) = v;
    __nv_bfloat16 h[4], l[4];
    bf16_split(v.x, h[0], l[0]); bf16_split(v.y, h[1], l[1]);
    bf16_split(v.z, h[2], l[2]); bf16_split(v.w, h[3], l[3]);
    *(uint2 *)(g_zhi + base) = make_uint2(pack2(h[0], h[1]), pack2(h[2], h[3]));
    *(uint2 *)(g_zlo + base) = make_uint2(pack2(l[0], l[1]), pack2(l[2], l[3]));
}

__global__ void __launch_bounds__(256)
wsplit_kernel(const float *__restrict__ src, int which) {
    const int base = (blockIdx.x * 256 + threadIdx.x) * 4;
    __nv_bfloat16 *dh = which ? g_W2hi : g_W1hi;
    __nv_bfloat16 *dl = which ? g_W2lo : g_W1lo;
    const float4 v = *(const float4 *)(src + base);
    __nv_bfloat16 h[4], l[4];
    bf16_split(v.x, h[0], l[0]); bf16_split(v.y, h[1], l[1]);
    bf16_split(v.z, h[2], l[2]); bf16_split(v.w, h[3], l[3]);
    *(uint2 *)(dh + base) = make_uint2(pack2(h[0], h[1]), pack2(h[2], h[3]));
    *(uint2 *)(dl + base) = make_uint2(pack2(l[0], l[1]), pack2(l[2], l[3]));
}

// [T][B*Z] -> [B*Z][T]
__global__ void __launch_bounds__(256)
transpose_kernel(float *__restrict__ out) {
    __shared__ float sm[32][33];
    const int p0 = blockIdx.x * 32;
    const int t0 = blockIdx.y * 32;
    const int tx = threadIdx.x;
    const int ty = threadIdx.y;
#pragma unroll
    for (int i = 0; i < 4; i++) {
        const int tl = ty + 8 * i;
        sm[tl][tx] = g_traj[(size_t)(t0 + tl) * NP + p0 + tx];
    }
    __syncthreads();
#pragma unroll
    for (int i = 0; i < 4; i++) {
        const int pl = ty + 8 * i;
        out[(size_t)(p0 + pl) * NT + t0 + tx] = sm[tx][pl];
    }
}

// ---------------------------------------------------------------------------
extern "C" void kernel_launch(void *const *d_in, const int *in_sizes, int n_in,
                              void *d_out, int out_size) {
    const float *z0 = (const float *)d_in[0];
    const float *ts = (const float *)d_in[1];
    const float *W1 = (const float *)d_in[2];
    const float *wt = (const float *)d_in[3];
    const float *b1 = (const float *)d_in[4];
    const float *W2 = (const float *)d_in[5];
    const float *b2 = (const float *)d_in[6];
    float *out = (float *)d_out;

    wsplit_kernel<<<(HD * ZD) / 1024, 256>>>(W1, 0);
    wsplit_kernel<<<(HD * ZD) / 1024, 256>>>(W2, 1);
    init_kernel<<<NP / 1024, 256>>>(z0);

    for (int s = 0; s < NT - 1; ++s) {
        // partials of z @ W1^T (split-K=4): 256 CTAs x 256 thr
        gemm_mma<ZD, 0><<<dim3(HD / 64, NB / 128, SPLIT1), 256>>>();
        // h = tanh(sum + t*wt + b1) -> bf16 splits
        hsplit_kernel<<<(NB * HD) / 1024, 256>>>(wt, b1, ts, s);
        // partials of h @ W2^T (split-K=8): 256 CTAs x 256 thr
        gemm_mma<HD, 1><<<dim3(ZD / 64, NB / 128, SPLIT2), 256>>>();
        // z += dt*(dz + b2); trajectory slice s+1
        euler_kernel<<<NP / 1024, 256>>>(b2, ts, s);
    }

    transpose_kernel<<<dim3(NP / 32, NT / 32), dim3(32, 8)>>>(out);
}